// round 13
// baseline (speedup 1.0000x reference)
#include <cuda_runtime.h>
#include <cuda_bf16.h>
#include <cuda_fp16.h>
#include <math.h>

#define NTOK 2048
#define DMODEL 512
#define NQKV 1536
#define NHEADS 8
#define DHEAD 64

// ---------------- scratch (device globals) ----------------
__device__ __half g_strfh[NTOK * DMODEL];               // str_feat fp16
__device__ __half g_Wh[NQKV * DMODEL];                  // packed Wq|Wk|Wv fp16
__device__ float  g_b[NQKV];                            // packed bias f32
__device__ __half g_QKVh[NTOK * NQKV];                  // packed Q|K|V fp16
__device__ __half g_E[(size_t)NHEADS * NTOK * NTOK];    // exp(S/temp) fp16; later attn P
__device__ float  g_X[NTOK * DMODEL];                   // P @ V (f32)
__device__ float  g_xyz[2 * NTOK * 3];

__device__ __forceinline__ void mma_f16(float* c, unsigned a0, unsigned a1, unsigned a2, unsigned a3,
                                        unsigned b0, unsigned b1) {
    asm volatile("mma.sync.aligned.m16n8k16.row.col.f32.f16.f16.f32 "
                 "{%0,%1,%2,%3},{%4,%5,%6,%7},{%8,%9},{%0,%1,%2,%3};"
                 : "+f"(c[0]), "+f"(c[1]), "+f"(c[2]), "+f"(c[3])
                 : "r"(a0), "r"(a1), "r"(a2), "r"(a3), "r"(b0), "r"(b1));
}

// ================= generic f32 -> fp16 conversion (count = multiple of 1024) =================
__global__ void __launch_bounds__(256)
conv_f2h(const float* __restrict__ src, __half* __restrict__ dst)
{
    long i = (long)(blockIdx.x * 256 + threadIdx.x) * 4;
    float4 v = *(const float4*)(src + i);
    __half2 h0 = __floats2half2_rn(v.x, v.y);
    __half2 h1 = __floats2half2_rn(v.z, v.w);
    uint2 u;
    u.x = *(unsigned*)&h0; u.y = *(unsigned*)&h1;
    *(uint2*)(dst + i) = u;
}

// ================= QKV projection via f16 mma: QKVh = strfh @ Wh^T + bias, fp16 out =================
// C[2048 x 1536], K=512. CTA 128x128, BK=32. 256 thr = 8 warps 2(m) x 4(n), warp 64x32.
#define QPAD 40
__global__ void __launch_bounds__(256)
qkv_mma(const __half* __restrict__ Ah, const __half* __restrict__ Bh,
        const float* __restrict__ bias, __half* __restrict__ C)
{
    __shared__ __half As[128 * QPAD];
    __shared__ __half Bs[128 * QPAD];

    const int row0 = blockIdx.y * 128;
    const int col0 = blockIdx.x * 128;
    const int tid  = threadIdx.x;
    const int warp = tid >> 5, lane = tid & 31;
    const int wm = warp & 1, wn = warp >> 1;
    const int lq = lane >> 2, lr = lane & 3;

    float acc[4][4][4];
#pragma unroll
    for (int a = 0; a < 4; a++)
#pragma unroll
        for (int b = 0; b < 4; b++)
#pragma unroll
            for (int c = 0; c < 4; c++) acc[a][b][c] = 0.f;

    for (int k0 = 0; k0 < DMODEL; k0 += 32) {
        __syncthreads();
#pragma unroll
        for (int i = tid; i < 128 * 4; i += 256) {   // 4 uint4 (8 halves) per 32-col row
            int r = i >> 2, c8 = (i & 3) << 3;
            *(uint4*)(As + r*QPAD + c8) = *(const uint4*)(Ah + (long)(row0+r)*DMODEL + k0 + c8);
            *(uint4*)(Bs + r*QPAD + c8) = *(const uint4*)(Bh + (long)(col0+r)*DMODEL + k0 + c8);
        }
        __syncthreads();

#pragma unroll
        for (int kk = 0; kk < 2; kk++) {
            const int ca = kk * 16 + 2*lr;
            unsigned bf[4][2];
#pragma unroll
            for (int nt = 0; nt < 4; nt++) {
                int nb = wn*32 + nt*8 + lq;
                bf[nt][0] = *(const unsigned*)(Bs + nb*QPAD + ca);
                bf[nt][1] = *(const unsigned*)(Bs + nb*QPAD + ca + 8);
            }
#pragma unroll
            for (int mt = 0; mt < 4; mt++) {
                int ra = wm*64 + mt*16 + lq;
                unsigned a0 = *(const unsigned*)(As + ra*QPAD + ca);
                unsigned a1 = *(const unsigned*)(As + (ra+8)*QPAD + ca);
                unsigned a2 = *(const unsigned*)(As + ra*QPAD + ca + 8);
                unsigned a3 = *(const unsigned*)(As + (ra+8)*QPAD + ca + 8);
#pragma unroll
                for (int nt = 0; nt < 4; nt++)
                    mma_f16(acc[mt][nt], a0, a1, a2, a3, bf[nt][0], bf[nt][1]);
            }
        }
    }

#pragma unroll
    for (int mt = 0; mt < 4; mt++) {
#pragma unroll
        for (int nt = 0; nt < 4; nt++) {
            int r = row0 + wm*64 + mt*16 + lq;
            int c = col0 + wn*32 + nt*8 + 2*lr;
            float2 bb = *(const float2*)&bias[c];
            __half2 h0 = __floats2half2_rn(acc[mt][nt][0] + bb.x, acc[mt][nt][1] + bb.y);
            __half2 h1 = __floats2half2_rn(acc[mt][nt][2] + bb.x, acc[mt][nt][3] + bb.y);
            *(__half2*)(C + (long)r*NQKV + c)     = h0;
            *(__half2*)(C + (long)(r+8)*NQKV + c) = h1;
        }
    }
}

// ================= f32 NT GEMM (out projection): C = A*B^T + bias =================
template<int BM, int BN, int BK, int TM, int TN>
__global__ void __launch_bounds__((BM/TM)*(BN/TN), 2)
gemm_nt(int K,
        const float* __restrict__ A, int lda,
        const float* __restrict__ B, int ldb,
        float* __restrict__ C, int ldc,
        const float* __restrict__ bias)
{
    constexpr int THREADS = (BM/TM)*(BN/TN);
    constexpr int KV = BK/4;
    __shared__ float As[BK][BM];
    __shared__ float Bs[BK][BN];

    const int tid  = threadIdx.x;
    const int tcol = tid % (BN/TN);
    const int trow = tid / (BN/TN);
    const int row0 = blockIdx.y * BM;
    const int col0 = blockIdx.x * BN;

    float acc[TM][TN];
#pragma unroll
    for (int i = 0; i < TM; i++)
#pragma unroll
        for (int j = 0; j < TN; j++) acc[i][j] = 0.f;

    for (int k0 = 0; k0 < K; k0 += BK) {
#pragma unroll
        for (int i = tid; i < BM*KV; i += THREADS) {
            int m = i / KV, kv = i % KV;
            float4 v = *(const float4*)(A + (long)(row0+m)*lda + k0 + kv*4);
            As[kv*4+0][m] = v.x; As[kv*4+1][m] = v.y;
            As[kv*4+2][m] = v.z; As[kv*4+3][m] = v.w;
        }
#pragma unroll
        for (int i = tid; i < BN*KV; i += THREADS) {
            int nn = i / KV, kv = i % KV;
            float4 v = *(const float4*)(B + (long)(col0+nn)*ldb + k0 + kv*4);
            Bs[kv*4+0][nn] = v.x; Bs[kv*4+1][nn] = v.y;
            Bs[kv*4+2][nn] = v.z; Bs[kv*4+3][nn] = v.w;
        }
        __syncthreads();
#pragma unroll
        for (int kk = 0; kk < BK; kk++) {
            float a[TM], b[TN];
#pragma unroll
            for (int i = 0; i < TM; i += 4)
                *(float4*)&a[i] = *(const float4*)&As[kk][trow*TM + i];
#pragma unroll
            for (int j = 0; j < TN; j += 4)
                *(float4*)&b[j] = *(const float4*)&Bs[kk][tcol*TN + j];
#pragma unroll
            for (int i = 0; i < TM; i++)
#pragma unroll
                for (int j = 0; j < TN; j++)
                    acc[i][j] = fmaf(a[i], b[j], acc[i][j]);
        }
        __syncthreads();
    }

#pragma unroll
    for (int i = 0; i < TM; i++) {
        long r = row0 + trow*TM + i;
#pragma unroll
        for (int j = 0; j < TN; j += 4) {
            int c = col0 + tcol*TN + j;
            float4 v;
            v.x = acc[i][j+0]; v.y = acc[i][j+1];
            v.z = acc[i][j+2]; v.w = acc[i][j+3];
            float4 bb = *(const float4*)&bias[c];
            v.x += bb.x; v.y += bb.y; v.z += bb.z; v.w += bb.w;
            *(float4*)&C[r*ldc + c] = v;
        }
    }
}

// ================= scores via f16 mma: E[h] = exp((Qh@Kh^T)*0.125/temp), fp16 out =================
#define SPAD 72
__global__ void __launch_bounds__(256)
scores_mma(const __half* __restrict__ QKVh, __half* __restrict__ E,
           const float* __restrict__ tptr)
{
    __shared__ __half Qs[128 * SPAD];
    __shared__ __half Ks[128 * SPAD];

    const int h    = blockIdx.z;
    const int row0 = blockIdx.y * 128;
    const int col0 = blockIdx.x * 128;
    const int tid  = threadIdx.x;
    const int warp = tid >> 5, lane = tid & 31;
    const int wm = warp & 1, wn = warp >> 1;
    const int lq = lane >> 2;
    const int lr = lane & 3;

    const __half* Qg = QKVh + (long)row0 * NQKV + h * DHEAD;
    const __half* Kg = QKVh + (long)col0 * NQKV + DMODEL + h * DHEAD;

#pragma unroll
    for (int i = tid; i < 128 * 8; i += 256) {
        int r = i >> 3, c8 = (i & 7) << 3;
        *(uint4*)(Qs + r*SPAD + c8) = *(const uint4*)(Qg + (long)r * NQKV + c8);
        *(uint4*)(Ks + r*SPAD + c8) = *(const uint4*)(Kg + (long)r * NQKV + c8);
    }
    __syncthreads();

    float acc[4][4][4];
#pragma unroll
    for (int a = 0; a < 4; a++)
#pragma unroll
        for (int b = 0; b < 4; b++)
#pragma unroll
            for (int c = 0; c < 4; c++) acc[a][b][c] = 0.f;

#pragma unroll
    for (int kc = 0; kc < 4; kc++) {
        const int ca = kc * 16 + 2*lr;
        unsigned bf[4][2];
#pragma unroll
        for (int nt = 0; nt < 4; nt++) {
            int nb = wn*32 + nt*8 + lq;
            bf[nt][0] = *(const unsigned*)(Ks + nb*SPAD + ca);
            bf[nt][1] = *(const unsigned*)(Ks + nb*SPAD + ca + 8);
        }
#pragma unroll
        for (int mt = 0; mt < 4; mt++) {
            int ra = wm*64 + mt*16 + lq;
            unsigned a0 = *(const unsigned*)(Qs + ra*SPAD + ca);
            unsigned a1 = *(const unsigned*)(Qs + (ra+8)*SPAD + ca);
            unsigned a2 = *(const unsigned*)(Qs + ra*SPAD + ca + 8);
            unsigned a3 = *(const unsigned*)(Qs + (ra+8)*SPAD + ca + 8);
#pragma unroll
            for (int nt = 0; nt < 4; nt++)
                mma_f16(acc[mt][nt], a0, a1, a2, a3, bf[nt][0], bf[nt][1]);
        }
    }

    const float scale = 0.125f / tptr[0];
#pragma unroll
    for (int mt = 0; mt < 4; mt++) {
#pragma unroll
        for (int nt = 0; nt < 4; nt++) {
            int r = row0 + wm*64 + mt*16 + lq;
            int c = col0 + wn*32 + nt*8 + 2*lr;
            __half* b0 = E + ((long)h*NTOK + r)*NTOK + c;
            __half* b1 = E + ((long)h*NTOK + r + 8)*NTOK + c;
            *(__half2*)b0 = __floats2half2_rn(__expf(acc[mt][nt][0]*scale),
                                              __expf(acc[mt][nt][1]*scale));
            *(__half2*)b1 = __floats2half2_rn(__expf(acc[mt][nt][2]*scale),
                                              __expf(acc[mt][nt][3]*scale));
        }
    }
}

// ================= PV via f16 mma: X[h] = P[h] @ V[h], f32 out =================
#define PPAD 72
__global__ void __launch_bounds__(256)
pv_mma(const __half* __restrict__ P, const __half* __restrict__ QKVh,
       float* __restrict__ X)
{
    __shared__ __half Ps[64 * PPAD];
    __shared__ __half Vs[64 * PPAD];

    const int h    = blockIdx.z;
    const int row0 = blockIdx.y * 64;
    const int tid  = threadIdx.x;
    const int warp = tid >> 5, lane = tid & 31;
    const int wm = warp & 3, wn = warp >> 2;
    const int lq = lane >> 2, lr = lane & 3;

    const __half* Pg = P + ((long)h*NTOK + row0) * NTOK;
    const __half* Vg = QKVh + 2*DMODEL + h * DHEAD;   // V block, row stride NQKV

    float acc[4][4];
#pragma unroll
    for (int b = 0; b < 4; b++)
#pragma unroll
        for (int c = 0; c < 4; c++) acc[b][c] = 0.f;

    for (int k0 = 0; k0 < NTOK; k0 += 64) {
        __syncthreads();
#pragma unroll
        for (int i = tid; i < 512; i += 256) {
            int r = i >> 3, c8 = (i & 7) << 3;
            *(uint4*)(Ps + r*PPAD + c8) = *(const uint4*)(Pg + (long)r * NTOK + k0 + c8);
        }
#pragma unroll
        for (int i = tid; i < 2048; i += 256) {
            int k = i >> 5, np = i & 31;
            unsigned v = *(const unsigned*)(Vg + (long)(k0+k)*NQKV + 2*np);
            __half2 hv = *(__half2*)&v;
            Vs[(2*np)  *PPAD + k] = __low2half(hv);
            Vs[(2*np+1)*PPAD + k] = __high2half(hv);
        }
        __syncthreads();

#pragma unroll
        for (int ks = 0; ks < 4; ks++) {
            const int ca = ks * 16 + 2*lr;
            int ra = wm*16 + lq;
            unsigned a0 = *(const unsigned*)(Ps + ra*PPAD + ca);
            unsigned a1 = *(const unsigned*)(Ps + (ra+8)*PPAD + ca);
            unsigned a2 = *(const unsigned*)(Ps + ra*PPAD + ca + 8);
            unsigned a3 = *(const unsigned*)(Ps + (ra+8)*PPAD + ca + 8);
#pragma unroll
            for (int nt = 0; nt < 4; nt++) {
                int nb = wn*32 + nt*8 + lq;
                unsigned b0 = *(const unsigned*)(Vs + nb*PPAD + ca);
                unsigned b1 = *(const unsigned*)(Vs + nb*PPAD + ca + 8);
                mma_f16(acc[nt], a0, a1, a2, a3, b0, b1);
            }
        }
    }

    int r = row0 + wm*16 + lq;
#pragma unroll
    for (int nt = 0; nt < 4; nt++) {
        int c = h*DHEAD + wn*32 + nt*8 + 2*lr;
        *(float2*)&X[(long)r*DMODEL + c]     = make_float2(acc[nt][0], acc[nt][1]);
        *(float2*)&X[(long)(r+8)*DMODEL + c] = make_float2(acc[nt][2], acc[nt][3]);
    }
}

// ================= mean-shift step (fp16 E, interleaved ws4 smem) =================
template<bool FINAL>
__global__ void __launch_bounds__(256)
step_kernel(__half* __restrict__ E,
            const float* __restrict__ xyz_in,
            float* __restrict__ xyz_out,
            const float* __restrict__ yhat,
            const int* __restrict__ mask,
            const float* __restrict__ bwptr)
{
    __shared__ float4 ws4[NTOK];        // (w, w*x, w*y, w*z)
    __shared__ float red[NHEADS][3];

    const int n    = blockIdx.x;
    const int tid  = threadIdx.x;
    const int warp = tid >> 5;
    const int lane = tid & 31;

    const float bw  = bwptr[0];
    const float cbw = 1.0f / (2.0f * bw * bw);
    const float xn = xyz_in[n*3+0];
    const float yn = xyz_in[n*3+1];
    const float zn = xyz_in[n*3+2];
    const float sqn = xn*xn + yn*yn + zn*zn;
    const int* mrow = mask + (long)n * NTOK;

    for (int m = tid; m < NTOK; m += 256) {
        float x = xyz_in[m*3+0];
        float y = xyz_in[m*3+1];
        float z = xyz_in[m*3+2];
        float w = __expf(-(sqn + (x*x + y*y + z*z) - 2.f*(xn*x + yn*y + zn*z)) * cbw)
                  * yhat[m] + 1e-9f;
        w = (mrow[m] > 0) ? w : 0.f;
        ws4[m] = make_float4(w, w*x, w*y, w*z);
    }
    __syncthreads();

    __half* Eh = E + ((long)warp * NTOK + n) * NTOK;
    const uint2* Erow = (const uint2*)Eh;

    float Z = 0.f, ax = 0.f, ay = 0.f, az = 0.f;
#pragma unroll 8
    for (int it = 0; it < 16; it++) {
        int i4 = it*32 + lane;
        uint2 ee = Erow[i4];
        float2 e01 = __half22float2(*(__half2*)&ee.x);
        float2 e23 = __half22float2(*(__half2*)&ee.y);
        int j = i4 * 4;
        float4 q0 = ws4[j+0];
        float4 q1 = ws4[j+1];
        float4 q2 = ws4[j+2];
        float4 q3 = ws4[j+3];
        Z  = fmaf(e01.x, q0.x, fmaf(e01.y, q1.x, fmaf(e23.x, q2.x, fmaf(e23.y, q3.x, Z))));
        ax = fmaf(e01.x, q0.y, fmaf(e01.y, q1.y, fmaf(e23.x, q2.y, fmaf(e23.y, q3.y, ax))));
        ay = fmaf(e01.x, q0.z, fmaf(e01.y, q1.z, fmaf(e23.x, q2.z, fmaf(e23.y, q3.z, ay))));
        az = fmaf(e01.x, q0.w, fmaf(e01.y, q1.w, fmaf(e23.x, q2.w, fmaf(e23.y, q3.w, az))));
    }

#pragma unroll
    for (int o = 16; o; o >>= 1) {
        Z  += __shfl_xor_sync(0xffffffffu, Z, o);
        ax += __shfl_xor_sync(0xffffffffu, ax, o);
        ay += __shfl_xor_sync(0xffffffffu, ay, o);
        az += __shfl_xor_sync(0xffffffffu, az, o);
    }

    if (FINAL) {
        float invZ = 1.0f / Z;
        uint2* ErowW = (uint2*)Eh;
#pragma unroll 8
        for (int it = 0; it < 16; it++) {
            int i4 = it*32 + lane;
            uint2 ee = Erow[i4];
            float2 e01 = __half22float2(*(__half2*)&ee.x);
            float2 e23 = __half22float2(*(__half2*)&ee.y);
            int j = i4 * 4;
            __half2 p01 = __floats2half2_rn(e01.x*ws4[j+0].x*invZ, e01.y*ws4[j+1].x*invZ);
            __half2 p23 = __floats2half2_rn(e23.x*ws4[j+2].x*invZ, e23.y*ws4[j+3].x*invZ);
            uint2 o2;
            o2.x = *(unsigned*)&p01; o2.y = *(unsigned*)&p23;
            ErowW[i4] = o2;
        }
    }

    if (lane == 0) {
        float iZ = 1.0f / Z;
        red[warp][0] = ax * iZ;
        red[warp][1] = ay * iZ;
        red[warp][2] = az * iZ;
    }
    __syncthreads();
    if (tid == 0) {
        float X = 0.f, Y = 0.f, W = 0.f;
#pragma unroll
        for (int hh = 0; hh < NHEADS; hh++) { X += red[hh][0]; Y += red[hh][1]; W += red[hh][2]; }
        xyz_out[n*3+0] = X * 0.125f;
        xyz_out[n*3+1] = Y * 0.125f;
        xyz_out[n*3+2] = W * 0.125f;
    }
}

// ================= host orchestration =================
extern "C" void kernel_launch(void* const* d_in, const int* in_sizes, int n_in,
                              void* d_out, int out_size)
{
    const float* xyz  = (const float*)d_in[0];
    const float* strf = (const float*)d_in[1];
    // d_in[2] esm_feat: dead code in reference
    const float* yhat = (const float*)d_in[3];
    const int*   mask = (const int*)d_in[4];
    const float* t    = (const float*)d_in[5];
    const float* bw   = (const float*)d_in[6];
    // d_in[7] max_iter == 5 (static graph)
    const float* Wq = (const float*)d_in[8];
    const float* bq = (const float*)d_in[9];
    const float* Wk = (const float*)d_in[10];
    const float* bk = (const float*)d_in[11];
    const float* Wv = (const float*)d_in[12];
    const float* bv = (const float*)d_in[13];
    const float* Wo = (const float*)d_in[14];
    const float* bo = (const float*)d_in[15];

    float *bb, *X, *xyzb;
    __half *strfh, *Wh, *QKVh, *E;
    cudaGetSymbolAddress((void**)&strfh, g_strfh);
    cudaGetSymbolAddress((void**)&Wh,    g_Wh);
    cudaGetSymbolAddress((void**)&bb,    g_b);
    cudaGetSymbolAddress((void**)&QKVh,  g_QKVh);
    cudaGetSymbolAddress((void**)&E,     g_E);
    cudaGetSymbolAddress((void**)&X,     g_X);
    cudaGetSymbolAddress((void**)&xyzb,  g_xyz);

    float* xyz0 = xyzb;
    float* xyz1 = xyzb + NTOK*3;
    float* outp = (float*)d_out;

    cudaMemcpyAsync(bb + 0*DMODEL, bq, DMODEL*sizeof(float), cudaMemcpyDeviceToDevice);
    cudaMemcpyAsync(bb + 1*DMODEL, bk, DMODEL*sizeof(float), cudaMemcpyDeviceToDevice);
    cudaMemcpyAsync(bb + 2*DMODEL, bv, DMODEL*sizeof(float), cudaMemcpyDeviceToDevice);
    cudaMemcpyAsync(xyz0, xyz, NTOK*3*sizeof(float), cudaMemcpyDeviceToDevice);

    dim3 blk(256);

    // convert inputs to fp16
    conv_f2h<<<NTOK*DMODEL/4/256, blk>>>(strf, strfh);
    conv_f2h<<<DMODEL*DMODEL/4/256, blk>>>(Wq, Wh + 0*DMODEL*DMODEL);
    conv_f2h<<<DMODEL*DMODEL/4/256, blk>>>(Wk, Wh + 1*DMODEL*DMODEL);
    conv_f2h<<<DMODEL*DMODEL/4/256, blk>>>(Wv, Wh + 2*DMODEL*DMODEL);

    // fused QKV projection (f16 tensor cores), fp16 packed output
    qkv_mma<<<dim3(NQKV/128, NTOK/128), blk>>>(strfh, Wh, bb, QKVh);

    // scores (f16 tensor cores) -> E fp16
    scores_mma<<<dim3(NTOK/128, NTOK/128, NHEADS), blk>>>(QKVh, E, t);

    // 5 mean-shift iterations; final writes P (fp16) over E
    step_kernel<false><<<NTOK, blk>>>(E, xyz0, xyz1, yhat, mask, bw);
    step_kernel<false><<<NTOK, blk>>>(E, xyz1, xyz0, yhat, mask, bw);
    step_kernel<false><<<NTOK, blk>>>(E, xyz0, xyz1, yhat, mask, bw);
    step_kernel<false><<<NTOK, blk>>>(E, xyz1, xyz0, yhat, mask, bw);
    step_kernel<true ><<<NTOK, blk>>>(E, xyz0, xyz1, yhat, mask, bw);

    // X[h] = P[h] @ V[h]  (f16 tensor cores)
    pv_mma<<<dim3(1, NTOK/64, NHEADS), blk>>>(E, QKVh, X);

    // out = X @ Wo^T + bo  (f32 FFMA — output precision)
    gemm_nt<64,128,32,4,8><<<dim3(DMODEL/128, NTOK/64, 1), blk>>>(
        DMODEL, X, DMODEL, Wo, DMODEL, outp + NTOK*3, DMODEL, bo);

    cudaMemcpyAsync(outp, xyz1, NTOK*3*sizeof(float), cudaMemcpyDeviceToDevice);
}